// round 4
// baseline (speedup 1.0000x reference)
#include <cuda_runtime.h>
#include <math.h>

#define NWIN 2048
#define NT   66
#define C    256
#define NH   8
#define HD   32
#define TOKN 2
#define QK_SCALE 0.17677669529663687f   // 1/sqrt(32)

// shared memory layout (floats)
#define XS_STRIDE 260
#define QS_STRIDE 33
#define SS_STRIDE 67
#define WS_STRIDE 65

#define XS_OFF 0
#define OS_OFF (XS_OFF + NT*XS_STRIDE)          // 17160
#define WS_OFF (OS_OFF + NT*XS_STRIDE)          // 34320
#define QS_OFF (WS_OFF + 96*WS_STRIDE)          // 40560
#define KS_OFF (QS_OFF + NT*QS_STRIDE)          // 42738
#define VS_OFF (KS_OFF + NT*QS_STRIDE)          // 44916
#define SS_OFF (VS_OFF + NT*QS_STRIDE)          // 47094
#define SM_TOTAL (SS_OFF + NT*SS_STRIDE)        // 51516 floats = 206064 B

// Tiled GEMM: out[r][c] += sum_k xsrc[r][k] * Wg[grow(c)][k]
// 16x16 thread grid: thread owns up to 5 rows (rg+16i) x 6 cols (cg*6+j).
// mode 0: QKV slice for head h  -> grow = (c/32)*256 + h*32 + (c%32)
// mode 1: proj tile             -> grow = colbase + c   (guarded < 256)
__device__ __forceinline__ void gemm_tile(
    float* sm, int xoff, const float* __restrict__ Wg,
    int mode, int h, int colbase, int tid, float acc[5][6])
{
    const int cg = tid & 15;
    const int rg = tid >> 4;
    int roff[5];
#pragma unroll
    for (int i = 0; i < 5; i++) roff[i] = xoff + (rg + 16*i)*XS_STRIDE;

    for (int k0 = 0; k0 < C; k0 += 64) {
        __syncthreads();
        // stage W chunk [96 cols][64 k] into smem (float4 global reads)
        for (int idx = tid; idx < 96*16; idx += 256) {
            int c  = idx >> 4;
            int k4 = (idx & 15) * 4;
            int grow;
            if (mode == 0) grow = ((c >> 5) << 8) + (h << 5) + (c & 31);
            else           grow = colbase + c;
            if (mode == 0 || grow < C) {
                float4 w4 = *(const float4*)(Wg + (size_t)grow*C + k0 + k4);
                float* d = &sm[WS_OFF + c*WS_STRIDE + k4];
                d[0] = w4.x; d[1] = w4.y; d[2] = w4.z; d[3] = w4.w;
            }
        }
        __syncthreads();
        // accumulate
        const float* wsb = &sm[WS_OFF + (cg*6)*WS_STRIDE];
#pragma unroll 4
        for (int kk = 0; kk < 64; kk += 4) {
            float4 xv[5];
#pragma unroll
            for (int i = 0; i < 5; i++)
                xv[i] = *(const float4*)&sm[roff[i] + k0 + kk];
#pragma unroll
            for (int j = 0; j < 6; j++) {
                const float* wp = wsb + j*WS_STRIDE + kk;
                float w0 = wp[0], w1 = wp[1], w2 = wp[2], w3 = wp[3];
#pragma unroll
                for (int i = 0; i < 5; i++) {
                    acc[i][j] += xv[i].x * w0;
                    acc[i][j] += xv[i].y * w1;
                    acc[i][j] += xv[i].z * w2;
                    acc[i][j] += xv[i].w * w3;
                }
            }
        }
    }
}

__global__ __launch_bounds__(256, 1)
void winattn_kernel(const float* __restrict__ x,
                    const float* __restrict__ qkv_w,
                    const float* __restrict__ qkv_b,
                    const float* __restrict__ rbt,
                    const float* __restrict__ proj_w,
                    const float* __restrict__ proj_b,
                    float* __restrict__ out)
{
    extern __shared__ float sm[];
    const int tid  = threadIdx.x;
    const int b    = blockIdx.x;
    const int cg   = tid & 15;
    const int rg   = tid >> 4;
    const int lane = tid & 31;
    const int warp = tid >> 5;

    // ---- load x tile [66][256] into smem ----
    const float* xg = x + (size_t)b * NT * C;
    for (int idx = tid; idx < NT*C/4; idx += 256) {
        int n = (idx*4) / C;
        int k = (idx*4) % C;
        float4 v = *(const float4*)(xg + n*C + k);
        float* d = &sm[XS_OFF + n*XS_STRIDE + k];
        d[0] = v.x; d[1] = v.y; d[2] = v.z; d[3] = v.w;
    }
    // (gemm_tile's first internal __syncthreads covers the x-load barrier)

    // ---- per-head attention ----
    for (int h = 0; h < NH; h++) {
        float acc[5][6];
#pragma unroll
        for (int i = 0; i < 5; i++)
#pragma unroll
            for (int j = 0; j < 6; j++) acc[i][j] = 0.f;

        // q/k/v slices for this head: cols 0..31 = q, 32..63 = k, 64..95 = v
        gemm_tile(sm, XS_OFF, qkv_w, 0, h, 0, tid, acc);

        // epilogue: add bias, scale q, write q/k/v to smem
#pragma unroll
        for (int i = 0; i < 5; i++) {
            int r = rg + 16*i;
            if (r < NT) {
#pragma unroll
                for (int j = 0; j < 6; j++) {
                    int c = cg*6 + j;
                    int m = c >> 5, d = c & 31;
                    float v = acc[i][j] + qkv_b[(m << 8) + (h << 5) + d];
                    if      (m == 0) sm[QS_OFF + r*QS_STRIDE + d] = v * QK_SCALE;
                    else if (m == 1) sm[KS_OFF + r*QS_STRIDE + d] = v;
                    else             sm[VS_OFF + r*QS_STRIDE + d] = v;
                }
            }
        }
        __syncthreads();

        // scores: s[row][col] = q[row] . k[col] + rel_bias
        for (int idx = tid; idx < NT*NT; idx += 256) {
            int row = idx / NT, col = idx % NT;
            const float* qp = &sm[QS_OFF + row*QS_STRIDE];
            const float* kp = &sm[KS_OFF + col*QS_STRIDE];
            float s = 0.f;
#pragma unroll
            for (int k = 0; k < HD; k++) s += qp[k] * kp[k];
            if (row >= TOKN && col >= TOKN) {
                int i = row - TOKN, j = col - TOKN;
                int bi = (((i >> 3) - (j >> 3) + 7) * 15) + ((i & 7) - (j & 7) + 7);
                s += rbt[bi * NH + h];
            }
            sm[SS_OFF + row*SS_STRIDE + col] = s;
        }
        __syncthreads();

        // softmax over each row (one warp per row, rows strided by 8)
        for (int row = warp; row < NT; row += 8) {
            float* sp = &sm[SS_OFF + row*SS_STRIDE];
            float v0 = sp[lane];
            float v1 = sp[lane + 32];
            float v2 = (lane < NT - 64) ? sp[lane + 64] : -INFINITY;
            float mx = fmaxf(fmaxf(v0, v1), v2);
#pragma unroll
            for (int o = 16; o > 0; o >>= 1)
                mx = fmaxf(mx, __shfl_xor_sync(0xffffffffu, mx, o));
            float e0 = __expf(v0 - mx);
            float e1 = __expf(v1 - mx);
            float e2 = (lane < NT - 64) ? __expf(v2 - mx) : 0.f;
            float s = e0 + e1 + e2;
#pragma unroll
            for (int o = 16; o > 0; o >>= 1)
                s += __shfl_xor_sync(0xffffffffu, s, o);
            float inv = 1.f / s;
            sp[lane]      = e0 * inv;
            sp[lane + 32] = e1 * inv;
            if (lane < NT - 64) sp[lane + 64] = e2 * inv;
        }
        __syncthreads();

        // o_h = P @ V  (thread: d = lane, rows g+8i), write into os head slice
        {
            const int d = tid & 31;
            const int g = tid >> 5;
            float oacc[9];
#pragma unroll
            for (int i = 0; i < 9; i++) oacc[i] = 0.f;
            for (int k = 0; k < NT; k++) {
                float vv = sm[VS_OFF + k*QS_STRIDE + d];
#pragma unroll
                for (int i = 0; i < 9; i++) {
                    int r = g + 8*i;
                    if (r < NT)
                        oacc[i] += sm[SS_OFF + r*SS_STRIDE + k] * vv;
                }
            }
#pragma unroll
            for (int i = 0; i < 9; i++) {
                int r = g + 8*i;
                if (r < NT)
                    sm[OS_OFF + r*XS_STRIDE + (h << 5) + d] = oacc[i];
            }
        }
        // next-head staging begins with __syncthreads inside gemm_tile
    }

    __syncthreads();

    // ---- output projection: out = os @ proj_w^T + proj_b ----
    float* og = out + (size_t)b * NT * C;
    for (int t = 0; t < 3; t++) {
        float acc[5][6];
#pragma unroll
        for (int i = 0; i < 5; i++)
#pragma unroll
            for (int j = 0; j < 6; j++) acc[i][j] = 0.f;

        gemm_tile(sm, OS_OFF, proj_w, 1, 0, 96*t, tid, acc);

#pragma unroll
        for (int i = 0; i < 5; i++) {
            int r = rg + 16*i;
            if (r < NT) {
#pragma unroll
                for (int j = 0; j < 6; j++) {
                    int c = 96*t + cg*6 + j;
                    if (c < C)
                        og[r*C + c] = acc[i][j] + proj_b[c];
                }
            }
        }
        // loop-head sync inside gemm_tile protects ws reuse
    }
}

extern "C" void kernel_launch(void* const* d_in, const int* in_sizes, int n_in,
                              void* d_out, int out_size) {
    const float* x      = (const float*)d_in[0];
    const float* qkv_w  = (const float*)d_in[1];
    const float* qkv_b  = (const float*)d_in[2];
    const float* rbt    = (const float*)d_in[3];
    const float* proj_w = (const float*)d_in[4];
    const float* proj_b = (const float*)d_in[5];
    float* out = (float*)d_out;

    size_t smem = (size_t)SM_TOTAL * sizeof(float);   // 206064 B
    cudaFuncSetAttribute(winattn_kernel,
                         cudaFuncAttributeMaxDynamicSharedMemorySize, (int)smem);
    winattn_kernel<<<NWIN, 256, smem>>>(x, qkv_w, qkv_b, rbt, proj_w, proj_b, out);
}

// round 13
// speedup vs baseline: 1.1788x; 1.1788x over previous
#include <cuda_runtime.h>
#include <cuda_fp16.h>
#include <math.h>
#include <stdint.h>

#define NWIN 2048
#define NT   66
#define NH   8
#define QK_SCALE 0.17677669529663687f
#define NTHREADS 512

// ---- smem byte offsets ----
#define XHI_B 0u                 // 80 rows x 264 halves x 2B = 42240
#define XLO_B 42240u
#define BH0_B 84480u             // 96 x 40 halves x 2B = 7680 each
#define BL0_B 92160u
#define BH1_B 99840u
#define BL1_B 107520u
#define QS_B  115200u            // 66*33*4 = 8712
#define KS_B  123912u
#define VS_B  132624u
#define SS_B  141336u            // 66*68*4 = 17952
#define OS_B  159296u            // 66*260*4 = 68640 (16B aligned)
#define SMEM_BYTES 227936u

static __device__ __forceinline__ uint32_t smem_u32(const void* p) {
    uint32_t a;
    asm("{ .reg .u64 t; cvta.to.shared.u64 t, %1; cvt.u32.u64 %0, t; }" : "=r"(a) : "l"(p));
    return a;
}

static __device__ __forceinline__ void ldsm4(uint32_t addr, uint32_t r[4]) {
    asm volatile("ldmatrix.sync.aligned.m8n8.x4.shared.b16 {%0,%1,%2,%3}, [%4];"
                 : "=r"(r[0]), "=r"(r[1]), "=r"(r[2]), "=r"(r[3]) : "r"(addr));
}
static __device__ __forceinline__ void mma16816(float d[4], const uint32_t a[4],
                                                uint32_t b0, uint32_t b1) {
    asm volatile("mma.sync.aligned.m16n8k16.row.col.f32.f16.f16.f32 "
                 "{%0,%1,%2,%3}, {%4,%5,%6,%7}, {%8,%9}, {%0,%1,%2,%3};"
                 : "+f"(d[0]), "+f"(d[1]), "+f"(d[2]), "+f"(d[3])
                 : "r"(a[0]), "r"(a[1]), "r"(a[2]), "r"(a[3]), "r"(b0), "r"(b1));
}

static __device__ __forceinline__ uint32_t packh(__half a, __half b) {
    __half2 h = __halves2half2(a, b);
    return *reinterpret_cast<uint32_t*>(&h);
}
static __device__ __forceinline__ void cvt_hilo(float4 v, uint2& uh, uint2& ul) {
    __half a0 = __float2half_rn(v.x), a1 = __float2half_rn(v.y),
           a2 = __float2half_rn(v.z), a3 = __float2half_rn(v.w);
    __half b0 = __float2half_rn(v.x - __half2float(a0)),
           b1 = __float2half_rn(v.y - __half2float(a1)),
           b2 = __float2half_rn(v.z - __half2float(a2)),
           b3 = __float2half_rn(v.w - __half2float(a3));
    uh.x = packh(a0, a1); uh.y = packh(a2, a3);
    ul.x = packh(b0, b1); ul.y = packh(b2, b3);
}

// ---- B-chunk staging: 96 rows x 32 k-floats per chunk ----
static __device__ __forceinline__ void b_ldg(
    const float* __restrict__ Wg, int mode, int h, int colbase, int nvalid,
    int kbase, int tid, float4 st[2])
{
#pragma unroll
    for (int u = 0; u < 2; u++) {
        int idx = tid + u * 512;
        if (idx < 768) {
            int n = idx >> 3, f4 = (idx & 7) << 2;
            if (n < nvalid) {
                int grow = mode ? (colbase + n) : (((n >> 5) << 8) | (h << 5) | (n & 31));
                st[u] = *(const float4*)(Wg + (size_t)grow * 256 + kbase + f4);
            } else {
                st[u] = make_float4(0.f, 0.f, 0.f, 0.f);
            }
        }
    }
}
static __device__ __forceinline__ void b_sts(
    char* smb, int buf, int tid, const float4 st[2])
{
    uint32_t bh = buf ? BH1_B : BH0_B;
    uint32_t bl = buf ? BL1_B : BL0_B;
#pragma unroll
    for (int u = 0; u < 2; u++) {
        int idx = tid + u * 512;
        if (idx < 768) {
            int n = idx >> 3, f4 = idx & 7;
            uint2 uh, ul;
            cvt_hilo(st[u], uh, ul);
            *(uint2*)(smb + bh + n * 80 + f4 * 8) = uh;
            *(uint2*)(smb + bl + n * 80 + f4 * 8) = ul;
        }
    }
}

// ---- one k32 chunk of MMAs for a warp tile m16 x n32 (3-pass hi/lo split) ----
static __device__ __forceinline__ void mma_chunk(
    uint32_t smu, int buf, int kbase_h, int wm, int wn, int lane, float acc[4][4])
{
    uint32_t bh = buf ? BH1_B : BH0_B;
    uint32_t bl = buf ? BL1_B : BL0_B;
    uint32_t rowA = (uint32_t)(wm * 16 + (lane & 15));
    uint32_t aoff = rowA * 528u + (uint32_t)((lane >> 4) * 16);
    uint32_t nloc = (uint32_t)(((lane >> 4) << 3) + (lane & 7));
    uint32_t boff = (uint32_t)(wn * 32 + nloc) * 80u + (uint32_t)(((lane >> 3) & 1) * 16);
#pragma unroll
    for (int s = 0; s < 2; s++) {
        uint32_t kg = (uint32_t)(kbase_h + s * 16);
        uint32_t ah[4], al[4], bh0[4], bh1[4], bl0[4], bl1[4];
        ldsm4(smu + XHI_B + aoff + kg * 2, ah);
        ldsm4(smu + XLO_B + aoff + kg * 2, al);
        uint32_t bk = (uint32_t)(s * 32);
        ldsm4(smu + bh + boff + bk, bh0);
        ldsm4(smu + bh + boff + 1280 + bk, bh1);
        ldsm4(smu + bl + boff + bk, bl0);
        ldsm4(smu + bl + boff + 1280 + bk, bl1);
        mma16816(acc[0], ah, bh0[0], bh0[1]);
        mma16816(acc[1], ah, bh0[2], bh0[3]);
        mma16816(acc[2], ah, bh1[0], bh1[1]);
        mma16816(acc[3], ah, bh1[2], bh1[3]);
        mma16816(acc[0], ah, bl0[0], bl0[1]);
        mma16816(acc[1], ah, bl0[2], bl0[3]);
        mma16816(acc[2], ah, bl1[0], bl1[1]);
        mma16816(acc[3], ah, bl1[2], bl1[3]);
        mma16816(acc[0], al, bh0[0], bh0[1]);
        mma16816(acc[1], al, bh0[2], bh0[3]);
        mma16816(acc[2], al, bh1[0], bh1[1]);
        mma16816(acc[3], al, bh1[2], bh1[3]);
    }
}

// ---- full K=256 GEMM: pipelined B staging + warp MMAs ----
static __device__ __forceinline__ void gemm_full(
    const float* __restrict__ Wg, int mode, int h, int colbase, int nvalid,
    char* smb, uint32_t smu, int tid, int warp, int lane, float acc[4][4])
{
    const int wm = warp / 3, wn = warp % 3;
    float4 st[2];
    b_ldg(Wg, mode, h, colbase, nvalid, 0, tid, st);
    b_sts(smb, 0, tid, st);
    __syncthreads();
#pragma unroll 1
    for (int c = 0; c < 8; c++) {
        if (c < 7) b_ldg(Wg, mode, h, colbase, nvalid, (c + 1) * 32, tid, st);
        if (warp < 15) mma_chunk(smu, c & 1, c * 32, wm, wn, lane, acc);
        if (c < 7) b_sts(smb, (c + 1) & 1, tid, st);
        __syncthreads();
    }
}

__global__ __launch_bounds__(NTHREADS, 1)
void winattn_mma(const float* __restrict__ x,
                 const float* __restrict__ qkv_w,
                 const float* __restrict__ qkv_b,
                 const float* __restrict__ rbt,
                 const float* __restrict__ proj_w,
                 const float* __restrict__ proj_b,
                 float* __restrict__ out)
{
    extern __shared__ char smb[];
    const uint32_t smu = smem_u32(smb);
    float* QSf = (float*)(smb + QS_B);
    float* KSf = (float*)(smb + KS_B);
    float* VSf = (float*)(smb + VS_B);
    float* SSf = (float*)(smb + SS_B);
    float* OSf = (float*)(smb + OS_B);

    const int tid  = threadIdx.x;
    const int warp = tid >> 5;
    const int lane = tid & 31;
    const int wm = warp / 3, wn = warp % 3;
    const int b = blockIdx.x;
    const float* xg = x + (size_t)b * NT * 256;
    float* og = out + (size_t)b * NT * 256;

    // ---- stage X -> fp16 hi/lo smem (rows 0-65), zero pad rows 66-79 ----
    for (int idx = tid; idx < NT * 64; idx += NTHREADS) {
        int n = idx >> 6, c4 = (idx & 63) << 2;
        float4 v = *(const float4*)(xg + n * 256 + c4);
        uint2 uh, ul;
        cvt_hilo(v, uh, ul);
        *(uint2*)(smb + XHI_B + n * 528 + c4 * 2) = uh;
        *(uint2*)(smb + XLO_B + n * 528 + c4 * 2) = ul;
    }
    {
        uint4 z = make_uint4(0u, 0u, 0u, 0u);
        for (int idx = tid; idx < 14 * 33; idx += NTHREADS) {
            int r = 66 + idx / 33, q = idx % 33;
            *(uint4*)(smb + XHI_B + r * 528 + q * 16) = z;
            *(uint4*)(smb + XLO_B + r * 528 + q * 16) = z;
        }
    }
    // (covered by gemm_full's first __syncthreads before any MMA)

    const int c1 = lane + 32;
    const bool has2 = (lane < 2);
    const int c2 = lane + 64;

    for (int h = 0; h < NH; h++) {
        float acc[4][4];
#pragma unroll
        for (int j = 0; j < 4; j++)
#pragma unroll
            for (int q = 0; q < 4; q++) acc[j][q] = 0.f;

        gemm_full(qkv_w, 0, h, 0, 96, smb, smu, tid, warp, lane, acc);

        // ---- QKV epilogue: acc -> QS/KS/VS with bias (+q scale) ----
        if (warp < 15) {
            int r0 = wm * 16 + (lane >> 2);
            int r1 = r0 + 8;
#pragma unroll
            for (int j = 0; j < 4; j++) {
                int col = wn * 32 + j * 8 + ((lane & 3) << 1);
                int m = col >> 5, d = col & 31;
                float bias0 = qkv_b[(m << 8) + (h << 5) + d];
                float bias1 = qkv_b[(m << 8) + (h << 5) + d + 1];
                float sc = (m == 0) ? QK_SCALE : 1.f;
                float* dst = (m == 0) ? QSf : (m == 1) ? KSf : VSf;
                if (r0 < NT) {
                    dst[r0 * 33 + d]     = (acc[j][0] + bias0) * sc;
                    dst[r0 * 33 + d + 1] = (acc[j][1] + bias1) * sc;
                }
                if (r1 < NT) {
                    dst[r1 * 33 + d]     = (acc[j][2] + bias0) * sc;
                    dst[r1 * 33 + d + 1] = (acc[j][3] + bias1) * sc;
                }
            }
        }
        __syncthreads();

        // ---- scores + rel-pos bias (verified logic) ----
        for (int idx = tid; idx < NT * NT; idx += NTHREADS) {
            int row = idx / NT, col = idx % NT;
            const float* qp = &QSf[row * 33];
            const float* kp = &KSf[col * 33];
            float s = 0.f;
#pragma unroll
            for (int k = 0; k < 32; k++) s += qp[k] * kp[k];
            if (row >= 2 && col >= 2) {
                int i = row - 2, j = col - 2;
                int bi = (((i >> 3) - (j >> 3) + 7) * 15) + ((i & 7) - (j & 7) + 7);
                s += rbt[bi * NH + h];
            }
            SSf[row * 68 + col] = s;
        }
        __syncthreads();

        // ---- softmax (one warp per row, stride 16) ----
        for (int row = warp; row < NT; row += 16) {
            float* sp = &SSf[row * 68];
            float v0 = sp[lane], v1 = sp[c1];
            float v2 = has2 ? sp[c2] : -INFINITY;
            float mx = fmaxf(fmaxf(v0, v1), v2);
#pragma unroll
            for (int o = 16; o > 0; o >>= 1)
                mx = fmaxf(mx, __shfl_xor_sync(0xffffffffu, mx, o));
            float e0 = __expf(v0 - mx), e1 = __expf(v1 - mx);
            float e2 = has2 ? __expf(v2 - mx) : 0.f;
            float s = e0 + e1 + e2;
#pragma unroll
            for (int o = 16; o > 0; o >>= 1)
                s += __shfl_xor_sync(0xffffffffu, s, o);
            float inv = 1.f / s;
            sp[lane] = e0 * inv; sp[c1] = e1 * inv;
            if (has2) sp[c2] = e2 * inv;
        }
        __syncthreads();

        // ---- PV: 16 warps, rows warp+16i, d=lane ----
        {
            float oacc[5];
#pragma unroll
            for (int i = 0; i < 5; i++) oacc[i] = 0.f;
            for (int k = 0; k < NT; k++) {
                float vv = VSf[k * 33 + lane];
#pragma unroll
                for (int i = 0; i < 5; i++) {
                    int r = warp + 16 * i;
                    if (r < NT) oacc[i] += SSf[r * 68 + k] * vv;
                }
            }
#pragma unroll
            for (int i = 0; i < 5; i++) {
                int r = warp + 16 * i;
                if (r < NT) OSf[r * 260 + (h << 5) + lane] = oacc[i];
            }
        }
        __syncthreads();
    }

    // ---- restage O -> fp16 hi/lo (rows 0-65; pad rows still zero) ----
    for (int idx = tid; idx < NT * 64; idx += NTHREADS) {
        int n = idx >> 6, c4 = (idx & 63) << 2;
        float4 v = *(const float4*)&OSf[n * 260 + c4];
        uint2 uh, ul;
        cvt_hilo(v, uh, ul);
        *(uint2*)(smb + XHI_B + n * 528 + c4 * 2) = uh;
        *(uint2*)(smb + XLO_B + n * 528 + c4 * 2) = ul;
    }
    // (covered by gemm_full's first __syncthreads)

    // ---- output projection: N=256 in 3 chunks of 96 (last padded to 64 valid) ----
#pragma unroll 1
    for (int t = 0; t < 3; t++) {
        int nvalid = (t == 2) ? 64 : 96;
        float acc[4][4];
#pragma unroll
        for (int j = 0; j < 4; j++)
#pragma unroll
            for (int q = 0; q < 4; q++) acc[j][q] = 0.f;

        gemm_full(proj_w, 1, 0, 96 * t, nvalid, smb, smu, tid, warp, lane, acc);

        if (warp < 15) {
            int r0 = wm * 16 + (lane >> 2);
            int r1 = r0 + 8;
#pragma unroll
            for (int j = 0; j < 4; j++) {
                int col = 96 * t + wn * 32 + j * 8 + ((lane & 3) << 1);
                if (col < 256) {
                    float pb0 = proj_b[col], pb1 = proj_b[col + 1];
                    if (r0 < NT) {
                        float2 v; v.x = acc[j][0] + pb0; v.y = acc[j][1] + pb1;
                        *(float2*)(og + r0 * 256 + col) = v;
                    }
                    if (r1 < NT) {
                        float2 v; v.x = acc[j][2] + pb0; v.y = acc[j][3] + pb1;
                        *(float2*)(og + r1 * 256 + col) = v;
                    }
                }
            }
        }
        __syncthreads();
    }
}

extern "C" void kernel_launch(void* const* d_in, const int* in_sizes, int n_in,
                              void* d_out, int out_size) {
    const float* x      = (const float*)d_in[0];
    const float* qkv_w  = (const float*)d_in[1];
    const float* qkv_b  = (const float*)d_in[2];
    const float* rbt    = (const float*)d_in[3];
    const float* proj_w = (const float*)d_in[4];
    const float* proj_b = (const float*)d_in[5];
    float* out = (float*)d_out;

    cudaFuncSetAttribute(winattn_mma,
                         cudaFuncAttributeMaxDynamicSharedMemorySize, SMEM_BYTES);
    winattn_mma<<<NWIN, NTHREADS, SMEM_BYTES>>>(x, qkv_w, qkv_b, rbt, proj_w, proj_b, out);
}

// round 14
// speedup vs baseline: 2.4432x; 2.0726x over previous
#include <cuda_runtime.h>
#include <cuda_fp16.h>
#include <math.h>
#include <stdint.h>

#define NWIN 2048
#define NT   66
#define NH   8
#define QK_SCALE 0.17677669529663687f
#define NTHREADS 512

// ---- smem byte offsets ----
#define XHI_B 0u                 // 80 rows x 264 halves x 2B = 42240
#define XLO_B 42240u
#define BH0_B 84480u             // B staging: 96 x 40 halves x 2B = 7680 each
#define BL0_B 92160u
#define BH1_B 99840u
#define BL1_B 107520u
// overlays on the B-staging region (alive only between QKV gemm and next gemm):
#define QA_HI 84480u             // Q as A-op: 80 rows x 40 halves (stride 80B)
#define QA_LO 90880u
#define KB_HI 97280u             // K as B-op: 96 rows x 40 halves
#define KB_LO 104960u
#define SS2_B 84480u             // fp32 scores 66x68, overlays QA/KB after scores mma
// persistent middle buffers (zero-padded once):
#define VT_HI 115200u            // V^T as B-op: 32 rows x 88 halves (stride 176B)
#define VT_LO 120832u
#define PA_HI 126464u            // P as A-op: 80 rows x 88 halves (stride 176B)
#define PA_LO 140544u
#define OS_B  159296u            // 66*260*4 = 68640
#define SMEM_BYTES 227936u

static __device__ __forceinline__ uint32_t smem_u32(const void* p) {
    uint32_t a;
    asm("{ .reg .u64 t; cvta.to.shared.u64 t, %1; cvt.u32.u64 %0, t; }" : "=r"(a) : "l"(p));
    return a;
}

static __device__ __forceinline__ void ldsm4(uint32_t addr, uint32_t r[4]) {
    asm volatile("ldmatrix.sync.aligned.m8n8.x4.shared.b16 {%0,%1,%2,%3}, [%4];"
                 : "=r"(r[0]), "=r"(r[1]), "=r"(r[2]), "=r"(r[3]) : "r"(addr));
}
static __device__ __forceinline__ void mma16816(float d[4], const uint32_t a[4],
                                                uint32_t b0, uint32_t b1) {
    asm volatile("mma.sync.aligned.m16n8k16.row.col.f32.f16.f16.f32 "
                 "{%0,%1,%2,%3}, {%4,%5,%6,%7}, {%8,%9}, {%0,%1,%2,%3};"
                 : "+f"(d[0]), "+f"(d[1]), "+f"(d[2]), "+f"(d[3])
                 : "r"(a[0]), "r"(a[1]), "r"(a[2]), "r"(a[3]), "r"(b0), "r"(b1));
}
// acc[0..3] are the four n8 tiles of an n32 warp tile
static __device__ __forceinline__ void mma_block(
    float acc[4][4], const uint32_t a[4], const uint32_t b0[4], const uint32_t b1[4])
{
    mma16816(acc[0], a, b0[0], b0[1]);
    mma16816(acc[1], a, b0[2], b0[3]);
    mma16816(acc[2], a, b1[0], b1[1]);
    mma16816(acc[3], a, b1[2], b1[3]);
}

static __device__ __forceinline__ uint32_t packh(__half a, __half b) {
    __half2 h = __halves2half2(a, b);
    return *reinterpret_cast<uint32_t*>(&h);
}
static __device__ __forceinline__ void hilo1(float v, __half& h, __half& l) {
    h = __float2half_rn(v);
    l = __float2half_rn(v - __half2float(h));
}
static __device__ __forceinline__ void cvt_hilo(float4 v, uint2& uh, uint2& ul) {
    __half a0, a1, a2, a3, b0, b1, b2, b3;
    hilo1(v.x, a0, b0); hilo1(v.y, a1, b1);
    hilo1(v.z, a2, b2); hilo1(v.w, a3, b3);
    uh.x = packh(a0, a1); uh.y = packh(a2, a3);
    ul.x = packh(b0, b1); ul.y = packh(b2, b3);
}

// ---- B-chunk staging: 96 rows x 32 k-floats per chunk ----
static __device__ __forceinline__ void b_ldg(
    const float* __restrict__ Wg, int mode, int h, int colbase, int nvalid,
    int kbase, int tid, float4 st[2])
{
#pragma unroll
    for (int u = 0; u < 2; u++) {
        int idx = tid + u * 512;
        if (idx < 768) {
            int n = idx >> 3, f4 = (idx & 7) << 2;
            if (n < nvalid) {
                int grow = mode ? (colbase + n) : (((n >> 5) << 8) | (h << 5) | (n & 31));
                st[u] = *(const float4*)(Wg + (size_t)grow * 256 + kbase + f4);
            } else {
                st[u] = make_float4(0.f, 0.f, 0.f, 0.f);
            }
        }
    }
}
static __device__ __forceinline__ void b_sts(
    char* smb, int buf, int tid, const float4 st[2])
{
    uint32_t bh = buf ? BH1_B : BH0_B;
    uint32_t bl = buf ? BL1_B : BL0_B;
#pragma unroll
    for (int u = 0; u < 2; u++) {
        int idx = tid + u * 512;
        if (idx < 768) {
            int n = idx >> 3, f4 = idx & 7;
            uint2 uh, ul;
            cvt_hilo(st[u], uh, ul);
            *(uint2*)(smb + bh + n * 80 + f4 * 8) = uh;
            *(uint2*)(smb + bl + n * 80 + f4 * 8) = ul;
        }
    }
}

// ---- one k32 chunk of MMAs for a warp tile m16 x n32 (3-pass hi/lo split) ----
static __device__ __forceinline__ void mma_chunk(
    uint32_t smu, int buf, int kbase_h, int wm, int wn, int lane, float acc[4][4])
{
    uint32_t bh = buf ? BH1_B : BH0_B;
    uint32_t bl = buf ? BL1_B : BL0_B;
    uint32_t rowA = (uint32_t)(wm * 16 + (lane & 15));
    uint32_t aoff = rowA * 528u + (uint32_t)((lane >> 4) * 16);
    uint32_t nloc = (uint32_t)(((lane >> 4) << 3) + (lane & 7));
    uint32_t boff = (uint32_t)(wn * 32 + nloc) * 80u + (uint32_t)(((lane >> 3) & 1) * 16);
#pragma unroll
    for (int s = 0; s < 2; s++) {
        uint32_t kg = (uint32_t)(kbase_h + s * 16);
        uint32_t ah[4], al[4], bh0[4], bh1[4], bl0[4], bl1[4];
        ldsm4(smu + XHI_B + aoff + kg * 2, ah);
        ldsm4(smu + XLO_B + aoff + kg * 2, al);
        uint32_t bk = (uint32_t)(s * 32);
        ldsm4(smu + bh + boff + bk, bh0);
        ldsm4(smu + bh + boff + 1280 + bk, bh1);
        ldsm4(smu + bl + boff + bk, bl0);
        ldsm4(smu + bl + boff + 1280 + bk, bl1);
        mma_block(acc, ah, bh0, bh1);
        mma_block(acc, ah, bl0, bl1);
        mma_block(acc, al, bh0, bh1);
    }
}

// ---- full K=256 GEMM: pipelined B staging + warp MMAs ----
static __device__ __forceinline__ void gemm_full(
    const float* __restrict__ Wg, int mode, int h, int colbase, int nvalid,
    char* smb, uint32_t smu, int tid, int warp, int lane, float acc[4][4])
{
    const int wm = warp / 3, wn = warp % 3;
    float4 st[2];
    b_ldg(Wg, mode, h, colbase, nvalid, 0, tid, st);
    b_sts(smb, 0, tid, st);
    __syncthreads();
#pragma unroll 1
    for (int c = 0; c < 8; c++) {
        if (c < 7) b_ldg(Wg, mode, h, colbase, nvalid, (c + 1) * 32, tid, st);
        if (warp < 15) mma_chunk(smu, c & 1, c * 32, wm, wn, lane, acc);
        if (c < 7) b_sts(smb, (c + 1) & 1, tid, st);
        __syncthreads();
    }
}

__global__ __launch_bounds__(NTHREADS, 1)
void winattn_mma(const float* __restrict__ x,
                 const float* __restrict__ qkv_w,
                 const float* __restrict__ qkv_b,
                 const float* __restrict__ rbt,
                 const float* __restrict__ proj_w,
                 const float* __restrict__ proj_b,
                 float* __restrict__ out)
{
    extern __shared__ char smb[];
    const uint32_t smu = smem_u32(smb);
    float* SSf = (float*)(smb + SS2_B);
    float* OSf = (float*)(smb + OS_B);

    const int tid  = threadIdx.x;
    const int warp = tid >> 5;
    const int lane = tid & 31;
    const int wm = warp / 3, wn = warp % 3;
    const int b = blockIdx.x;
    const float* xg = x + (size_t)b * NT * 256;
    float* og = out + (size_t)b * NT * 256;

    // ---- stage X -> fp16 hi/lo smem (rows 0-65), zero pad rows 66-79 ----
    for (int idx = tid; idx < NT * 64; idx += NTHREADS) {
        int n = idx >> 6, c4 = (idx & 63) << 2;
        float4 v = *(const float4*)(xg + n * 256 + c4);
        uint2 uh, ul;
        cvt_hilo(v, uh, ul);
        *(uint2*)(smb + XHI_B + n * 528 + c4 * 2) = uh;
        *(uint2*)(smb + XLO_B + n * 528 + c4 * 2) = ul;
    }
    {
        uint4 z = make_uint4(0u, 0u, 0u, 0u);
        for (int idx = tid; idx < 14 * 33; idx += NTHREADS) {
            int r = 66 + idx / 33, q = idx % 33;
            *(uint4*)(smb + XHI_B + r * 528 + q * 16) = z;
            *(uint4*)(smb + XLO_B + r * 528 + q * 16) = z;
        }
        // zero VT + PA (contiguous 115200..154624 = 39424 B)
        for (int idx = tid; idx < 2464; idx += NTHREADS)
            *(uint4*)(smb + VT_HI + idx * 16) = z;
    }
    // (first gemm_full's internal __syncthreads orders these before use)

    const int c1 = lane + 32;
    const bool has2 = (lane < 2);
    const int c2 = lane + 64;

    for (int h = 0; h < NH; h++) {
        float acc[4][4];
#pragma unroll
        for (int j = 0; j < 4; j++)
#pragma unroll
            for (int q = 0; q < 4; q++) acc[j][q] = 0.f;

        gemm_full(qkv_w, 0, h, 0, 96, smb, smu, tid, warp, lane, acc);

        // ---- QKV epilogue: fragments -> fp16 hi/lo operand buffers ----
        if (warp < 15) {
            int r0 = wm * 16 + (lane >> 2), r1 = r0 + 8;
#pragma unroll
            for (int j = 0; j < 4; j++) {
                int col = wn * 32 + j * 8 + ((lane & 3) << 1);
                int m = col >> 5, d = col & 31;
                float bb0 = qkv_b[(m << 8) + (h << 5) + d];
                float bb1 = qkv_b[(m << 8) + (h << 5) + d + 1];
                float x0 = acc[j][0] + bb0, x1 = acc[j][1] + bb1;
                float x2 = acc[j][2] + bb0, x3 = acc[j][3] + bb1;
                if (m == 0) { x0 *= QK_SCALE; x1 *= QK_SCALE; x2 *= QK_SCALE; x3 *= QK_SCALE; }
                __half h0, l0, h1, l1, h2, l2, h3, l3;
                hilo1(x0, h0, l0); hilo1(x1, h1, l1);
                hilo1(x2, h2, l2); hilo1(x3, h3, l3);
                if (m < 2) {
                    uint32_t bhb = (m == 0) ? QA_HI : KB_HI;
                    uint32_t blb = (m == 0) ? QA_LO : KB_LO;
                    if (r0 < NT) {
                        *(uint32_t*)(smb + bhb + r0 * 80 + d * 2) = packh(h0, h1);
                        *(uint32_t*)(smb + blb + r0 * 80 + d * 2) = packh(l0, l1);
                    }
                    if (r1 < NT) {
                        *(uint32_t*)(smb + bhb + r1 * 80 + d * 2) = packh(h2, h3);
                        *(uint32_t*)(smb + blb + r1 * 80 + d * 2) = packh(l2, l3);
                    }
                } else {  // v transposed: VT[d][token]
                    if (r0 < NT) {
                        *(__half*)(smb + VT_HI + d * 176 + r0 * 2)       = h0;
                        *(__half*)(smb + VT_HI + (d + 1) * 176 + r0 * 2) = h1;
                        *(__half*)(smb + VT_LO + d * 176 + r0 * 2)       = l0;
                        *(__half*)(smb + VT_LO + (d + 1) * 176 + r0 * 2) = l1;
                    }
                    if (r1 < NT) {
                        *(__half*)(smb + VT_HI + d * 176 + r1 * 2)       = h2;
                        *(__half*)(smb + VT_HI + (d + 1) * 176 + r1 * 2) = h3;
                        *(__half*)(smb + VT_LO + d * 176 + r1 * 2)       = l2;
                        *(__half*)(smb + VT_LO + (d + 1) * 176 + r1 * 2) = l3;
                    }
                }
            }
        }
        __syncthreads();

        // ---- scores MMA: S[80x80] = Q[80x32] @ K^T, 3-pass hi/lo ----
        float sacc[4][4];
#pragma unroll
        for (int j = 0; j < 4; j++)
#pragma unroll
            for (int q = 0; q < 4; q++) sacc[j][q] = 0.f;
        if (warp < 15) {
            uint32_t aoffq = (uint32_t)((wm * 16 + (lane & 15)) * 80 + ((lane >> 4) << 4));
            uint32_t nloc = (uint32_t)(((lane >> 4) << 3) + (lane & 7));
            uint32_t boffk = (uint32_t)((wn * 32 + nloc) * 80 + (((lane >> 3) & 1) << 4));
#pragma unroll
            for (int s = 0; s < 2; s++) {
                uint32_t ko = (uint32_t)(s * 32);
                uint32_t qh[4], ql[4], kh0[4], kh1[4], kl0[4], kl1[4];
                ldsm4(smu + QA_HI + aoffq + ko, qh);
                ldsm4(smu + QA_LO + aoffq + ko, ql);
                ldsm4(smu + KB_HI + boffk + ko, kh0);
                ldsm4(smu + KB_HI + boffk + 1280u + ko, kh1);
                ldsm4(smu + KB_LO + boffk + ko, kl0);
                ldsm4(smu + KB_LO + boffk + 1280u + ko, kl1);
                mma_block(sacc, qh, kh0, kh1);
                mma_block(sacc, qh, kl0, kl1);
                mma_block(sacc, ql, kh0, kh1);
            }
        }
        __syncthreads();   // all reads of QA/KB done before SSf overlays them

        // ---- scores epilogue: + rel-pos bias -> SSf fp32 ----
        if (warp < 15) {
            int r0 = wm * 16 + (lane >> 2);
#pragma unroll
            for (int j = 0; j < 4; j++) {
                int col = wn * 32 + j * 8 + ((lane & 3) << 1);
#pragma unroll
                for (int e = 0; e < 4; e++) {
                    int r = (e < 2) ? r0 : r0 + 8;
                    int c = col + (e & 1);
                    if (r < NT && c < NT) {
                        float s = sacc[j][e];
                        if (r >= 2 && c >= 2) {
                            int i2 = r - 2, j2 = c - 2;
                            int bi = (((i2 >> 3) - (j2 >> 3) + 7) * 15)
                                   + ((i2 & 7) - (j2 & 7) + 7);
                            s += rbt[bi * NH + h];
                        }
                        SSf[r * 68 + c] = s;
                    }
                }
            }
        }
        __syncthreads();

        // ---- softmax: SSf -> P fp16 hi/lo fragments ----
        for (int row = warp; row < NT; row += 16) {
            float* sp = &SSf[row * 68];
            float v0 = sp[lane], v1 = sp[c1];
            float v2 = has2 ? sp[c2] : -INFINITY;
            float mx = fmaxf(fmaxf(v0, v1), v2);
#pragma unroll
            for (int o = 16; o > 0; o >>= 1)
                mx = fmaxf(mx, __shfl_xor_sync(0xffffffffu, mx, o));
            float e0 = __expf(v0 - mx), e1 = __expf(v1 - mx);
            float e2 = has2 ? __expf(v2 - mx) : 0.f;
            float s = e0 + e1 + e2;
#pragma unroll
            for (int o = 16; o > 0; o >>= 1)
                s += __shfl_xor_sync(0xffffffffu, s, o);
            float inv = 1.f / s;
            __half ph, pl;
            hilo1(e0 * inv, ph, pl);
            *(__half*)(smb + PA_HI + row * 176 + lane * 2) = ph;
            *(__half*)(smb + PA_LO + row * 176 + lane * 2) = pl;
            hilo1(e1 * inv, ph, pl);
            *(__half*)(smb + PA_HI + row * 176 + c1 * 2) = ph;
            *(__half*)(smb + PA_LO + row * 176 + c1 * 2) = pl;
            if (has2) {
                hilo1(e2 * inv, ph, pl);
                *(__half*)(smb + PA_HI + row * 176 + c2 * 2) = ph;
                *(__half*)(smb + PA_LO + row * 176 + c2 * 2) = pl;
            }
        }
        __syncthreads();

        // ---- PV MMA: O[80x32] = P[80x80] @ V, warps 0-4, 3-pass ----
        if (warp < 5) {
            float pacc[4][4];
#pragma unroll
            for (int j = 0; j < 4; j++)
#pragma unroll
                for (int q = 0; q < 4; q++) pacc[j][q] = 0.f;
            uint32_t aoffp = (uint32_t)((warp * 16 + (lane & 15)) * 176 + ((lane >> 4) << 4));
            uint32_t nloc = (uint32_t)(((lane >> 4) << 3) + (lane & 7));
            uint32_t boffv = (uint32_t)(nloc * 176 + (((lane >> 3) & 1) << 4));
#pragma unroll
            for (int s = 0; s < 5; s++) {
                uint32_t ko = (uint32_t)(s * 32);
                uint32_t ph4[4], pl4[4], vh0[4], vh1[4], vl0[4], vl1[4];
                ldsm4(smu + PA_HI + aoffp + ko, ph4);
                ldsm4(smu + PA_LO + aoffp + ko, pl4);
                ldsm4(smu + VT_HI + boffv + ko, vh0);
                ldsm4(smu + VT_HI + boffv + 2816u + ko, vh1);
                ldsm4(smu + VT_LO + boffv + ko, vl0);
                ldsm4(smu + VT_LO + boffv + 2816u + ko, vl1);
                mma_block(pacc, ph4, vh0, vh1);
                mma_block(pacc, ph4, vl0, vl1);
                mma_block(pacc, pl4, vh0, vh1);
            }
            int r0 = warp * 16 + (lane >> 2), r1 = r0 + 8;
#pragma unroll
            for (int j = 0; j < 4; j++) {
                int c = j * 8 + ((lane & 3) << 1);
                if (r0 < NT) {
                    float2 v; v.x = pacc[j][0]; v.y = pacc[j][1];
                    *(float2*)&OSf[r0 * 260 + (h << 5) + c] = v;
                }
                if (r1 < NT) {
                    float2 v; v.x = pacc[j][2]; v.y = pacc[j][3];
                    *(float2*)&OSf[r1 * 260 + (h << 5) + c] = v;
                }
            }
        }
        __syncthreads();
    }

    // ---- restage O -> fp16 hi/lo (rows 0-65; pad rows still zero) ----
    for (int idx = tid; idx < NT * 64; idx += NTHREADS) {
        int n = idx >> 6, c4 = (idx & 63) << 2;
        float4 v = *(const float4*)&OSf[n * 260 + c4];
        uint2 uh, ul;
        cvt_hilo(v, uh, ul);
        *(uint2*)(smb + XHI_B + n * 528 + c4 * 2) = uh;
        *(uint2*)(smb + XLO_B + n * 528 + c4 * 2) = ul;
    }
    // (covered by gemm_full's first __syncthreads)

    // ---- output projection: N=256 in 3 chunks of 96 (last 64 valid) ----
#pragma unroll 1
    for (int t = 0; t < 3; t++) {
        int nvalid = (t == 2) ? 64 : 96;
        float acc[4][4];
#pragma unroll
        for (int j = 0; j < 4; j++)
#pragma unroll
            for (int q = 0; q < 4; q++) acc[j][q] = 0.f;

        gemm_full(proj_w, 1, 0, 96 * t, nvalid, smb, smu, tid, warp, lane, acc);

        if (warp < 15) {
            int r0 = wm * 16 + (lane >> 2), r1 = r0 + 8;
#pragma unroll
            for (int j = 0; j < 4; j++) {
                int col = 96 * t + wn * 32 + j * 8 + ((lane & 3) << 1);
                if (col < 256) {
                    float pb0 = proj_b[col], pb1 = proj_b[col + 1];
                    if (r0 < NT) {
                        float2 v; v.x = acc[j][0] + pb0; v.y = acc[j][1] + pb1;
                        *(float2*)(og + r0 * 256 + col) = v;
                    }
                    if (r1 < NT) {
                        float2 v; v.x = acc[j][2] + pb0; v.y = acc[j][3] + pb1;
                        *(float2*)(og + r1 * 256 + col) = v;
                    }
                }
            }
        }
        __syncthreads();
    }
}

extern "C" void kernel_launch(void* const* d_in, const int* in_sizes, int n_in,
                              void* d_out, int out_size) {
    const float* x      = (const float*)d_in[0];
    const float* qkv_w  = (const float*)d_in[1];
    const float* qkv_b  = (const float*)d_in[2];
    const float* rbt    = (const float*)d_in[3];
    const float* proj_w = (const float*)d_in[4];
    const float* proj_b = (const float*)d_in[5];
    float* out = (float*)d_out;

    cudaFuncSetAttribute(winattn_mma,
                         cudaFuncAttributeMaxDynamicSharedMemorySize, SMEM_BYTES);
    winattn_mma<<<NWIN, NTHREADS, SMEM_BYTES>>>(x, qkv_w, qkv_b, rbt, proj_w, proj_b, out);
}